// round 10
// baseline (speedup 1.0000x reference)
#include <cuda_runtime.h>

// PS-ROI Pooling, direct windowed average.
// features [4,1029,64,64] f32, rois [1024,5] f32 (b,x1,y1,x2,y2),
// out [1024,21,7,7] f32.  GROUP_SIZE==POOLED==7 => chan == local out index.
//
// NUMERICS (round 10): golden = jax/XLA:GPU f32. XLA's GPU emitter lowers
// f32 division to div.full.f32 (fast, ~2ulp, NOT correctly rounded) via
// !fpmath metadata. bin = roi/7 computed with div.full differs by 1-2 ulp
// from div.rn; at the ~235 sites where the true bin end ((p+1)m+7K)/112 is
// EXACTLY an integer, that ulp decides ceil -> N vs N+1 (the entire fixed
// 24.9-energy mismatch, invariant across all my correctly-rounded rounds).
// __fdividef == div.full.f32 == the same PTX op XLA emits -> bitwise match.
// Boundary mul/add stay separate RN ops (eager jax = per-primitive kernels).

#define BATCH 4
#define POOLED 7
#define OUTPUT_DIM 21
#define CHANNELS (OUTPUT_DIM * POOLED * POOLED)  // 1029
#define H 64
#define W 64
#define SPATIAL_SCALE 0.0625f
#define NUM_ROIS 1024
#define PER_ROI CHANNELS                         // 1029
#define PLANE (H * W)

__global__ void psroi_v10_kernel(const float* __restrict__ features,
                                 const float* __restrict__ rois,
                                 float* __restrict__ out)
{
    __shared__ int sh_hs[POOLED], sh_he[POOLED];
    __shared__ int sh_ws[POOLED], sh_we[POOLED];
    __shared__ int sh_b;

    const int n   = blockIdx.x;
    const int tid = threadIdx.x;

    if (tid < 2 * POOLED) {
        const float* r = rois + n * 5;
        const int axis = tid / POOLED;   // 0 -> h (y: r[2],r[4]), 1 -> w (x: r[1],r[3])
        const int p    = tid % POOLED;

        float c_start = axis ? r[1] : r[2];
        float c_end   = axis ? r[3] : r[4];

        float rs = __fmul_rn(rintf(c_start), SPATIAL_SCALE);
        float re = __fmul_rn(rintf(__fadd_rn(c_end, 1.0f)), SPATIAL_SCALE);
        float roi_sz = fmaxf(__fsub_rn(re, rs), 0.1f);

        // div.full.f32 -- the XLA:GPU fast division. THE key change.
        float bin = __fdividef(roi_sz, (float)POOLED);

        float fp = (float)p;
        float v0 = __fadd_rn(__fmul_rn(fp, bin), rs);
        float v1 = __fadd_rn(__fmul_rn(__fadd_rn(fp, 1.0f), bin), rs);

        int s = (int)fminf(fmaxf(floorf(v0), 0.0f), 64.0f);
        int e = (int)fminf(fmaxf(ceilf (v1), 0.0f), 64.0f);

        if (axis == 0) { sh_hs[p] = s; sh_he[p] = e; }
        else           { sh_ws[p] = s; sh_we[p] = e; }
        if (tid == 0) sh_b = (int)r[0];
    }
    __syncthreads();

    const float* base = features + (size_t)sh_b * CHANNELS * PLANE;
    float* out_roi = out + (size_t)n * PER_ROI;

    for (int local = tid; local < PER_ROI; local += blockDim.x) {
        int pw = local % POOLED;
        int ph = (local / POOLED) % POOLED;

        int hs = sh_hs[ph], he = sh_he[ph];
        int ws = sh_ws[pw], we = sh_we[pw];

        const float* plane = base + (size_t)local * PLANE;

        float s = 0.0f;
        for (int h = hs; h < he; ++h) {
            const float* row = plane + h * W;
            for (int w = ws; w < we; ++w) {
                s = __fadd_rn(s, __ldg(row + w));
            }
        }

        int area = (he - hs) * (we - ws);
        // div.full.f32 here too, matching the golden's s / max(area, 1).
        out_roi[local] = (area > 0) ? __fdividef(s, (float)area) : 0.0f;
    }
}

extern "C" void kernel_launch(void* const* d_in, const int* in_sizes, int n_in,
                              void* d_out, int out_size)
{
    const float* features = (const float*)d_in[0];
    const float* rois     = (const float*)d_in[1];
    float* out            = (float*)d_out;

    psroi_v10_kernel<<<NUM_ROIS, 256>>>(features, rois, out);
}

// round 11
// speedup vs baseline: 1.1210x; 1.1210x over previous
#include <cuda_runtime.h>

// PS-ROI Pooling, float4-vectorized windowed average.
// features [4,1029,64,64] f32, rois [1024,5] f32, out [1024,21,7,7] f32.
//
// NUMERICS CONTRACT (frozen, validated R10: rel_err 9.5e-7):
//  - bounds: separate __fmul_rn/__fadd_rn, rintf, and __fdividef
//    (div.full.f32 == XLA:GPU's fast f32 division) for bin = roi/7.
//  - output division via __fdividef as well.
//  - window sum exact f32; order-insensitive at this tolerance.
//
// PERF (R11): windows are contiguous [ws,we) per row (width<=6) within one
// plane; lanes of a warp hit 32 different planes, so L1 wavefronts ~= 32 per
// warp-LDG. Cut warp-LDG count ~1.75x by loading each row as 1-3 aligned
// float4 chunks with precomputed 0/1 masks, FMA-accumulated.

#define BATCH 4
#define POOLED 7
#define OUTPUT_DIM 21
#define CHANNELS (OUTPUT_DIM * POOLED * POOLED)  // 1029
#define H 64
#define W 64
#define SPATIAL_SCALE 0.0625f
#define NUM_ROIS 1024
#define PER_ROI CHANNELS                         // 1029
#define PLANE (H * W)

__global__ void psroi_v11_kernel(const float* __restrict__ features,
                                 const float* __restrict__ rois,
                                 float* __restrict__ out)
{
    __shared__ int sh_hs[POOLED], sh_he[POOLED];
    __shared__ int sh_ws[POOLED], sh_we[POOLED];
    __shared__ int sh_b;

    const int n   = blockIdx.x;
    const int tid = threadIdx.x;

    if (tid < 2 * POOLED) {
        const float* r = rois + n * 5;
        const int axis = tid / POOLED;   // 0 -> h (y: r[2],r[4]), 1 -> w (x: r[1],r[3])
        const int p    = tid % POOLED;

        float c_start = axis ? r[1] : r[2];
        float c_end   = axis ? r[3] : r[4];

        float rs = __fmul_rn(rintf(c_start), SPATIAL_SCALE);
        float re = __fmul_rn(rintf(__fadd_rn(c_end, 1.0f)), SPATIAL_SCALE);
        float roi_sz = fmaxf(__fsub_rn(re, rs), 0.1f);
        float bin    = __fdividef(roi_sz, (float)POOLED);   // div.full.f32 (XLA match)

        float fp = (float)p;
        float v0 = __fadd_rn(__fmul_rn(fp, bin), rs);
        float v1 = __fadd_rn(__fmul_rn(__fadd_rn(fp, 1.0f), bin), rs);

        int s = (int)fminf(fmaxf(floorf(v0), 0.0f), 64.0f);
        int e = (int)fminf(fmaxf(ceilf (v1), 0.0f), 64.0f);

        if (axis == 0) { sh_hs[p] = s; sh_he[p] = e; }
        else           { sh_ws[p] = s; sh_we[p] = e; }
        if (tid == 0) sh_b = (int)r[0];
    }
    __syncthreads();

    const float* base = features + (size_t)sh_b * CHANNELS * PLANE;
    float* out_roi = out + (size_t)n * PER_ROI;

    for (int local = tid; local < PER_ROI; local += blockDim.x) {
        int pw = local % POOLED;
        int ph = (local / POOLED) % POOLED;

        int hs = sh_hs[ph], he = sh_he[ph];
        int ws = sh_ws[pw], we = sh_we[pw];

        // float4 chunk range covering [ws, we) within a 64-float row.
        int fc = ws >> 2;
        int lc = (we - 1) >> 2;          // we==0 (empty) -> lc = -1 < fc
        int nc = lc - fc + 1;            // 1..3 when non-empty

        // Row-invariant 0/1 masks for up to 3 chunks.
        float4 msk[3];
#pragma unroll
        for (int k = 0; k < 3; ++k) {
            int b0 = (fc + k) * 4;
            msk[k].x = (b0 + 0 >= ws && b0 + 0 < we) ? 1.0f : 0.0f;
            msk[k].y = (b0 + 1 >= ws && b0 + 1 < we) ? 1.0f : 0.0f;
            msk[k].z = (b0 + 2 >= ws && b0 + 2 < we) ? 1.0f : 0.0f;
            msk[k].w = (b0 + 3 >= ws && b0 + 3 < we) ? 1.0f : 0.0f;
        }

        const float* plane = base + (size_t)local * PLANE;

        float ax = 0.0f, ay = 0.0f, az = 0.0f, aw = 0.0f;
        for (int h = hs; h < he; ++h) {
            const float4* r4 = (const float4*)(plane + h * W) + fc;
#pragma unroll 3
            for (int k = 0; k < nc; ++k) {
                float4 v = __ldg(&r4[k]);
                ax = fmaf(v.x, msk[k].x, ax);
                ay = fmaf(v.y, msk[k].y, ay);
                az = fmaf(v.z, msk[k].z, az);
                aw = fmaf(v.w, msk[k].w, aw);
            }
        }
        float s = (ax + ay) + (az + aw);

        int area = (he - hs) * (we - ws);
        out_roi[local] = (area > 0) ? __fdividef(s, (float)area) : 0.0f;
    }
}

extern "C" void kernel_launch(void* const* d_in, const int* in_sizes, int n_in,
                              void* d_out, int out_size)
{
    const float* features = (const float*)d_in[0];
    const float* rois     = (const float*)d_in[1];
    float* out            = (float*)d_out;

    psroi_v11_kernel<<<NUM_ROIS, 256>>>(features, rois, out);
}